// round 10
// baseline (speedup 1.0000x reference)
#include <cuda_runtime.h>
#include <cstdint>
#include <cstddef>

#define S_LEN 1024
#define E_DIM 512
#define H_DIM 512
#define G3H   1536
#define D_DIM 1024
#define CL    16

typedef unsigned long long ull;

// ---------------- device scratch (static allocation only) ----------------
__device__ int   g_tokens[S_LEN];
__device__ float g_gi[(size_t)4 * S_LEN * G3H];   // 25.2 MB
__device__ float g_rep[4 * H_DIM];
__device__ float g_h1[D_DIM];

// ---------------- helpers ----------------
__device__ __forceinline__ float sigf(float x) { return 1.f / (1.f + __expf(-x)); }
__device__ __forceinline__ float tanhf_fast(float x) { return 2.f / (1.f + __expf(-2.f * x)) - 1.f; }

__device__ __forceinline__ uint32_t smem_u32(const void* p) {
    uint32_t a;
    asm("{ .reg .u64 t; cvta.to.shared.u64 t, %1; cvt.u32.u64 %0, t; }" : "=r"(a) : "l"(p));
    return a;
}

// ---------------- kernel -1: profiling-alignment no-op ----------------
__global__ void k_nop() {}

// ---------------- kernel 0: token dtype normalization ----------------
__global__ void k_tokens(const void* __restrict__ sent) {
    const int*       p32 = (const int*)sent;
    const long long* p64 = (const long long*)sent;
    bool is64 = true;
#pragma unroll
    for (int k = 0; k < 8; k++) {
        int lo = p32[2 * k], hi = p32[2 * k + 1];
        if (hi != 0 || lo < 0 || lo >= 50257) is64 = false;
    }
    int t = threadIdx.x;
    g_tokens[t] = is64 ? (int)p64[t] : p32[t];
}

// ---------------- kernel 1: gi = x @ Wih^T + bih (+ bhh folded for r,z) ----
__global__ __launch_bounds__(256, 2) void k_gemm_gi(
    const float* __restrict__ emb,
    const float* __restrict__ w0, const float* __restrict__ w1,
    const float* __restrict__ w2, const float* __restrict__ w3,
    const float* __restrict__ bi0, const float* __restrict__ bi1,
    const float* __restrict__ bi2, const float* __restrict__ bi3,
    const float* __restrict__ bh0, const float* __restrict__ bh1,
    const float* __restrict__ bh2, const float* __restrict__ bh3)
{
    int g = blockIdx.z;
    const float* Wih = (g == 0) ? w0 : (g == 1) ? w1 : (g == 2) ? w2 : w3;
    const float* bih = (g == 0) ? bi0 : (g == 1) ? bi1 : (g == 2) ? bi2 : bi3;
    const float* bhh = (g == 0) ? bh0 : (g == 1) ? bh1 : (g == 2) ? bh2 : bh3;

    int s0 = blockIdx.y * 128;
    int j0 = blockIdx.x * 128;
    int rev = g & 1;

    __shared__ float As[8][128];
    __shared__ float Bs[8][128];
    __shared__ int   toks[128];

    int tid = threadIdx.x;
    if (tid < 128) {
        int s = s0 + tid;
        toks[tid] = g_tokens[rev ? (S_LEN - 1 - s) : s];
    }
    __syncthreads();

    int tx = tid & 15, ty = tid >> 4;
    float acc[8][8];
#pragma unroll
    for (int i = 0; i < 8; i++)
#pragma unroll
        for (int j = 0; j < 8; j++) acc[i][j] = 0.f;

    int lrow = tid >> 1;
    int kq   = (tid & 1) * 4;
    const float* bptr = Wih + (size_t)(j0 + lrow) * E_DIM + kq;

    for (int kk = 0; kk < E_DIM; kk += 8) {
        float4 av = *(const float4*)(emb + (size_t)toks[lrow] * E_DIM + kk + kq);
        float4 bv = *(const float4*)(bptr + kk);
        As[kq + 0][lrow] = av.x; As[kq + 1][lrow] = av.y;
        As[kq + 2][lrow] = av.z; As[kq + 3][lrow] = av.w;
        Bs[kq + 0][lrow] = bv.x; Bs[kq + 1][lrow] = bv.y;
        Bs[kq + 2][lrow] = bv.z; Bs[kq + 3][lrow] = bv.w;
        __syncthreads();
#pragma unroll
        for (int k = 0; k < 8; k++) {
            float ar[8], br[8];
            *(float4*)&ar[0] = *(const float4*)&As[k][ty * 8];
            *(float4*)&ar[4] = *(const float4*)&As[k][ty * 8 + 4];
            *(float4*)&br[0] = *(const float4*)&Bs[k][tx * 8];
            *(float4*)&br[4] = *(const float4*)&Bs[k][tx * 8 + 4];
#pragma unroll
            for (int i = 0; i < 8; i++)
#pragma unroll
                for (int j = 0; j < 8; j++) acc[i][j] += ar[i] * br[j];
        }
        __syncthreads();
    }

#pragma unroll
    for (int i = 0; i < 8; i++) {
        int s = s0 + ty * 8 + i;
        float* orow = g_gi + ((size_t)g * S_LEN + s) * G3H;
#pragma unroll
        for (int j = 0; j < 8; j++) {
            int jg = j0 + tx * 8 + j;
            float bias = bih[jg] + (jg < 2 * H_DIM ? bhh[jg] : 0.f);
            orow[jg] = acc[i][j] + bias;
        }
    }
}

// ---------------- kernel 2: recurrent GRU, 4 clusters x 16 CTAs -------------
// Packed f32x2 matvec (5 reg rows + 1 SMEM row per warp), packed-shuffle
// butterfly reduce, redundant gate compute in every warp, warp w broadcasts
// only to peer w (1 remote store/thread), mbarrier double-buffered exchange.
__global__ void __cluster_dims__(CL, 1, 1) __launch_bounds__(512, 1)
k_gru(const float* __restrict__ u0, const float* __restrict__ u1,
      const float* __restrict__ u2, const float* __restrict__ u3,
      const float* __restrict__ bh0, const float* __restrict__ bh1,
      const float* __restrict__ bh2, const float* __restrict__ bh3)
{
    int crank = blockIdx.x & (CL - 1);
    int g     = blockIdx.x / CL;
    const float* Whh = (g == 0) ? u0 : (g == 1) ? u1 : (g == 2) ? u2 : u3;
    const float* bhh = (g == 0) ? bh0 : (g == 1) ? bh1 : (g == 2) ? bh2 : bh3;

    int tid = threadIdx.x, wid = tid >> 5, lane = tid & 31;
    int i_base = crank * 32;

    __shared__ ull   sh_w6[16][8][32];   // 32KB: row 5 of each warp
    __shared__ float sh_h[2][H_DIM];
    __shared__ float sh_gh[96];
    __shared__ float sh_bhhn[32];
    __shared__ ull   sh_mbar[2];
    __shared__ uint32_t sh_rh[CL];       // mapa'd peer base of sh_h[0][0]
    __shared__ uint32_t sh_rmb[CL];      // mapa'd peer base of sh_mbar[0]

    // Weights: warp wid owns rows fr = wid*6 .. wid*6+5; row fr -> gate fr>>5,
    // hidden idx i_base + (fr&31). Lane owns column pairs {64*jj + 2*lane, +1}.
    // Rows 0..4 -> registers; row 5 -> sh_w6 (keeps regs <= 128, no spills).
    ull w[5][8];
    int fr0 = wid * 6;
#pragma unroll
    for (int r = 0; r < 5; r++) {
        int fr   = fr0 + r;
        int grow = (fr >> 5) * H_DIM + i_base + (fr & 31);
        const ull* wp = (const ull*)(Whh + (size_t)grow * H_DIM + 2 * lane);
#pragma unroll
        for (int jj = 0; jj < 8; jj++) w[r][jj] = wp[jj * 32];
    }
    {
        int fr   = fr0 + 5;
        int grow = (fr >> 5) * H_DIM + i_base + (fr & 31);
        const ull* wp = (const ull*)(Whh + (size_t)grow * H_DIM + 2 * lane);
#pragma unroll
        for (int jj = 0; jj < 8; jj++) sh_w6[wid][jj][lane] = wp[jj * 32];
    }
    sh_h[0][tid] = 0.f;                       // blockDim == H_DIM
    if (tid < 32) sh_bhhn[tid] = bhh[2 * H_DIM + i_base + tid];

    uint32_t mbar0_l = smem_u32(&sh_mbar[0]);
    uint32_t h_l     = smem_u32(&sh_h[0][0]);
    if (tid == 0) {
        asm volatile("mbarrier.init.shared.b64 [%0], %1;" :: "r"(mbar0_l), "r"(CL) : "memory");
        asm volatile("mbarrier.init.shared.b64 [%0], %1;" :: "r"(mbar0_l + 8), "r"(CL) : "memory");
    }
    if (tid < CL) {
        uint32_t rh, rmb;
        asm("mapa.shared::cluster.u32 %0, %1, %2;" : "=r"(rh)  : "r"(h_l),     "r"(tid));
        asm("mapa.shared::cluster.u32 %0, %1, %2;" : "=r"(rmb) : "r"(mbar0_l), "r"(tid));
        sh_rh[tid]  = rh;
        sh_rmb[tid] = rmb;
    }
    __syncthreads();
    // all CTAs' mbarriers initialized before any remote store/arrive
    asm volatile("barrier.cluster.arrive.aligned;" ::: "memory");
    asm volatile("barrier.cluster.wait.aligned;" ::: "memory");

    const float* gi0    = g_gi + (size_t)g * S_LEN * G3H;
    uint32_t     w6base = smem_u32(&sh_w6[wid][0][lane]);   // +jj*256B per step
    uint32_t     my_rh  = sh_rh[wid];                        // peer this warp serves
    uint32_t     my_rmb = sh_rmb[wid];

    for (int s = 0; s < S_LEN; s++) {
        int p = s & 1;

        // prefetch gi (every warp needs it for its redundant gate compute)
        const float* gp = gi0 + (size_t)s * G3H + i_base + lane;
        float gir = gp[0];
        float giz = gp[H_DIM];
        float gin = gp[2 * H_DIM];

        if (s > 0) {
            uint32_t mb = mbar0_l + p * 8;
            uint32_t ph = ((s - 1) >> 1) & 1;
            asm volatile(
                "{\n\t.reg .pred P1;\n\t"
                "WL_%=:\n\t"
                "mbarrier.try_wait.parity.acquire.cluster.shared::cta.b64 P1, [%0], %1, 0x989680;\n\t"
                "@P1 bra.uni WD_%=;\n\t"
                "bra.uni WL_%=;\n\t"
                "WD_%=:\n\t}"
                :: "r"(mb), "r"(ph) : "memory");
        }

        // packed matvec: rows 0..4 from regs, row 5 streamed from SMEM
        ull a0 = 0, a1 = 0, a2 = 0, a3 = 0, a4 = 0, a5 = 0;
        const ull* hrow = (const ull*)&sh_h[p][2 * lane];
#pragma unroll
        for (int jj = 0; jj < 8; jj++) {
            ull hv = hrow[jj * 32];
            ull w5;
            asm("ld.shared.b64 %0, [%1];" : "=l"(w5) : "r"(w6base + jj * 256));
            asm("fma.rn.f32x2 %0, %1, %2, %0;" : "+l"(a0) : "l"(w[0][jj]), "l"(hv));
            asm("fma.rn.f32x2 %0, %1, %2, %0;" : "+l"(a1) : "l"(w[1][jj]), "l"(hv));
            asm("fma.rn.f32x2 %0, %1, %2, %0;" : "+l"(a2) : "l"(w[2][jj]), "l"(hv));
            asm("fma.rn.f32x2 %0, %1, %2, %0;" : "+l"(a3) : "l"(w[3][jj]), "l"(hv));
            asm("fma.rn.f32x2 %0, %1, %2, %0;" : "+l"(a4) : "l"(w[4][jj]), "l"(hv));
            asm("fma.rn.f32x2 %0, %1, %2, %0;" : "+l"(a5) : "l"(w5),       "l"(hv));
        }
        // fold pair halves, repack rows (r0,r1)(r2,r3)(r4,r5), packed butterfly
        float2 f0 = *(float2*)&a0, f1 = *(float2*)&a1, f2 = *(float2*)&a2;
        float2 f3 = *(float2*)&a3, f4 = *(float2*)&a4, f5 = *(float2*)&a5;
        ull v0, v1, v2;
        asm("mov.b64 %0, {%1, %2};" : "=l"(v0) : "f"(f0.x + f0.y), "f"(f1.x + f1.y));
        asm("mov.b64 %0, {%1, %2};" : "=l"(v1) : "f"(f2.x + f2.y), "f"(f3.x + f3.y));
        asm("mov.b64 %0, {%1, %2};" : "=l"(v2) : "f"(f4.x + f4.y), "f"(f5.x + f5.y));
#pragma unroll
        for (int off = 16; off > 0; off >>= 1) {
            ull o0 = __shfl_xor_sync(0xffffffffu, v0, off);
            ull o1 = __shfl_xor_sync(0xffffffffu, v1, off);
            ull o2 = __shfl_xor_sync(0xffffffffu, v2, off);
            asm("add.rn.f32x2 %0, %0, %1;" : "+l"(v0) : "l"(o0));
            asm("add.rn.f32x2 %0, %0, %1;" : "+l"(v1) : "l"(o1));
            asm("add.rn.f32x2 %0, %0, %1;" : "+l"(v2) : "l"(o2));
        }
        if (lane == 0) {
            *(ull*)&sh_gh[fr0 + 0] = v0;   // fr0 = 6*wid -> 8B aligned
            *(ull*)&sh_gh[fr0 + 2] = v1;
            *(ull*)&sh_gh[fr0 + 4] = v2;
        }
        __syncthreads();

        // every warp computes the full 32-gate slice (redundant, idle-lane work)
        float hold = sh_h[p][i_base + lane];
        float ghr  = sh_gh[lane];
        float ghz  = sh_gh[32 + lane];
        float ghn  = sh_gh[64 + lane];
        float rr = sigf(gir + ghr);
        float zz = sigf(giz + ghz);
        float nn = tanhf_fast(gin + rr * (ghn + sh_bhhn[lane]));
        float hn = (1.f - zz) * nn + zz * hold;

        if (s == S_LEN - 1) {
            if (wid == 0) g_rep[g * H_DIM + i_base + lane] = hn;
        } else {
            // warp w delivers this CTA's slice to peer w only (parallel DSMEM)
            uint32_t off = (uint32_t)(((p ^ 1) * H_DIM + i_base + lane) * 4);
            asm volatile("st.shared::cluster.f32 [%0], %1;"
                         :: "r"(my_rh + off), "f"(hn) : "memory");
            __syncwarp();
            if (lane == 0) {
                asm volatile("mbarrier.arrive.release.cluster.shared::cluster.b64 _, [%0];"
                             :: "r"(my_rmb + (uint32_t)((p ^ 1) * 8)) : "memory");
            }
        }
        // no step-end block barrier: readiness signaled by mbar[p^1]
    }
}

// ---------------- kernel 3/4: dense head ----------------
__global__ void k_dense1(const float* __restrict__ w, const float* __restrict__ b) {
    __shared__ float red[128];
    int d = blockIdx.x;
    const float* wr = w + (size_t)d * (4 * H_DIM);
    float s = 0.f;
    for (int k = threadIdx.x; k < 4 * H_DIM; k += 128) s += g_rep[k] * wr[k];
    red[threadIdx.x] = s;
    __syncthreads();
    for (int off = 64; off > 0; off >>= 1) {
        if (threadIdx.x < off) red[threadIdx.x] += red[threadIdx.x + off];
        __syncthreads();
    }
    if (threadIdx.x == 0) g_h1[d] = fmaxf(red[0] + b[d], 0.f);
}

__global__ void k_dense2(const float* __restrict__ w, const float* __restrict__ b,
                         float* __restrict__ out) {
    __shared__ float red[D_DIM];
    int t = threadIdx.x;
    red[t] = g_h1[t] * w[t];
    __syncthreads();
    for (int off = 512; off > 0; off >>= 1) {
        if (t < off) red[t] += red[t + off];
        __syncthreads();
    }
    if (t == 0) out[0] = 1.f / (1.f + __expf(-(red[0] + b[0])));
}

// ---------------- launch ----------------
extern "C" void kernel_launch(void* const* d_in, const int* in_sizes, int n_in,
                              void* d_out, int out_size)
{
    (void)in_sizes; (void)n_in; (void)out_size;
    const void*  sent = d_in[0];
    const float* emb  = (const float*)d_in[1];
    const float *wih[4], *whh[4], *bih[4], *bhh[4];
    for (int g = 0; g < 4; g++) {            // order: ctx_f, ctx_b, qry_f, qry_b
        wih[g] = (const float*)d_in[2 + 4 * g];
        whh[g] = (const float*)d_in[3 + 4 * g];
        bih[g] = (const float*)d_in[4 + 4 * g];
        bhh[g] = (const float*)d_in[5 + 4 * g];
    }
    const float* d1w = (const float*)d_in[18];
    const float* d1b = (const float*)d_in[19];
    const float* d2w = (const float*)d_in[20];
    const float* d2b = (const float*)d_in[21];

    cudaFuncSetAttribute(k_gru, cudaFuncAttributeNonPortableClusterSizeAllowed, 1);

    k_nop<<<1, 32>>>();                      // keeps k_gru inside ncu's capture window

    k_tokens<<<1, S_LEN>>>(sent);

    dim3 ggrid(G3H / 128, S_LEN / 128, 4);   // (12, 8, 4)
    k_gemm_gi<<<ggrid, 256>>>(emb,
                              wih[0], wih[1], wih[2], wih[3],
                              bih[0], bih[1], bih[2], bih[3],
                              bhh[0], bhh[1], bhh[2], bhh[3]);

    k_gru<<<64, 512>>>(whh[0], whh[1], whh[2], whh[3],
                       bhh[0], bhh[1], bhh[2], bhh[3]);

    k_dense1<<<D_DIM, 128>>>(d1w, d1b);
    k_dense2<<<1, D_DIM>>>(d2w, d2b, (float*)d_out);
}

// round 11
// speedup vs baseline: 1.0447x; 1.0447x over previous
#include <cuda_runtime.h>
#include <cstdint>
#include <cstddef>

#define S_LEN 1024
#define E_DIM 512
#define H_DIM 512
#define G3H   1536
#define D_DIM 1024
#define CL    16

typedef unsigned long long ull;

// ---------------- device scratch (static allocation only) ----------------
__device__ int   g_tokens[S_LEN];
__device__ float g_gi[(size_t)4 * S_LEN * G3H];   // 25.2 MB
__device__ float g_rep[4 * H_DIM];
__device__ float g_h1[D_DIM];

// ---------------- helpers ----------------
__device__ __forceinline__ float sigf(float x) { return 1.f / (1.f + __expf(-x)); }
__device__ __forceinline__ float tanhf_fast(float x) { return 2.f / (1.f + __expf(-2.f * x)) - 1.f; }

__device__ __forceinline__ uint32_t smem_u32(const void* p) {
    uint32_t a;
    asm("{ .reg .u64 t; cvta.to.shared.u64 t, %1; cvt.u32.u64 %0, t; }" : "=r"(a) : "l"(p));
    return a;
}

// ---------------- kernel -1: profiling-alignment no-op ----------------
__global__ void k_nop() {}

// ---------------- kernel 0: token dtype normalization ----------------
__global__ void k_tokens(const void* __restrict__ sent) {
    const int*       p32 = (const int*)sent;
    const long long* p64 = (const long long*)sent;
    bool is64 = true;
#pragma unroll
    for (int k = 0; k < 8; k++) {
        int lo = p32[2 * k], hi = p32[2 * k + 1];
        if (hi != 0 || lo < 0 || lo >= 50257) is64 = false;
    }
    int t = threadIdx.x;
    g_tokens[t] = is64 ? (int)p64[t] : p32[t];
}

// ---------------- kernel 1: gi = x @ Wih^T + bih (+ bhh folded for r,z) ----
__global__ __launch_bounds__(256, 2) void k_gemm_gi(
    const float* __restrict__ emb,
    const float* __restrict__ w0, const float* __restrict__ w1,
    const float* __restrict__ w2, const float* __restrict__ w3,
    const float* __restrict__ bi0, const float* __restrict__ bi1,
    const float* __restrict__ bi2, const float* __restrict__ bi3,
    const float* __restrict__ bh0, const float* __restrict__ bh1,
    const float* __restrict__ bh2, const float* __restrict__ bh3)
{
    int g = blockIdx.z;
    const float* Wih = (g == 0) ? w0 : (g == 1) ? w1 : (g == 2) ? w2 : w3;
    const float* bih = (g == 0) ? bi0 : (g == 1) ? bi1 : (g == 2) ? bi2 : bi3;
    const float* bhh = (g == 0) ? bh0 : (g == 1) ? bh1 : (g == 2) ? bh2 : bh3;

    int s0 = blockIdx.y * 128;
    int j0 = blockIdx.x * 128;
    int rev = g & 1;

    __shared__ float As[8][128];
    __shared__ float Bs[8][128];
    __shared__ int   toks[128];

    int tid = threadIdx.x;
    if (tid < 128) {
        int s = s0 + tid;
        toks[tid] = g_tokens[rev ? (S_LEN - 1 - s) : s];
    }
    __syncthreads();

    int tx = tid & 15, ty = tid >> 4;
    float acc[8][8];
#pragma unroll
    for (int i = 0; i < 8; i++)
#pragma unroll
        for (int j = 0; j < 8; j++) acc[i][j] = 0.f;

    int lrow = tid >> 1;
    int kq   = (tid & 1) * 4;
    const float* bptr = Wih + (size_t)(j0 + lrow) * E_DIM + kq;

    for (int kk = 0; kk < E_DIM; kk += 8) {
        float4 av = *(const float4*)(emb + (size_t)toks[lrow] * E_DIM + kk + kq);
        float4 bv = *(const float4*)(bptr + kk);
        As[kq + 0][lrow] = av.x; As[kq + 1][lrow] = av.y;
        As[kq + 2][lrow] = av.z; As[kq + 3][lrow] = av.w;
        Bs[kq + 0][lrow] = bv.x; Bs[kq + 1][lrow] = bv.y;
        Bs[kq + 2][lrow] = bv.z; Bs[kq + 3][lrow] = bv.w;
        __syncthreads();
#pragma unroll
        for (int k = 0; k < 8; k++) {
            float ar[8], br[8];
            *(float4*)&ar[0] = *(const float4*)&As[k][ty * 8];
            *(float4*)&ar[4] = *(const float4*)&As[k][ty * 8 + 4];
            *(float4*)&br[0] = *(const float4*)&Bs[k][tx * 8];
            *(float4*)&br[4] = *(const float4*)&Bs[k][tx * 8 + 4];
#pragma unroll
            for (int i = 0; i < 8; i++)
#pragma unroll
                for (int j = 0; j < 8; j++) acc[i][j] += ar[i] * br[j];
        }
        __syncthreads();
    }

#pragma unroll
    for (int i = 0; i < 8; i++) {
        int s = s0 + ty * 8 + i;
        float* orow = g_gi + ((size_t)g * S_LEN + s) * G3H;
#pragma unroll
        for (int j = 0; j < 8; j++) {
            int jg = j0 + tx * 8 + j;
            float bias = bih[jg] + (jg < 2 * H_DIM ? bhh[jg] : 0.f);
            orow[jg] = acc[i][j] + bias;
        }
    }
}

// ---------------- kernel 2: recurrent GRU, 4 clusters x 16 CTAs -------------
// R7 base + (a) 3-level butterfly with 4-partial SMEM handoff (SHFL traffic
// 288 vs 480 per SM per step) + (b) distributed DSMEM broadcast: warp 0 alone
// loads gi and computes gates; all 16 warps then deliver the slice, warp w ->
// peer w (1 remote store/thread instead of 16 serial on warp 0).
__global__ void __cluster_dims__(CL, 1, 1) __launch_bounds__(512, 1)
k_gru(const float* __restrict__ u0, const float* __restrict__ u1,
      const float* __restrict__ u2, const float* __restrict__ u3,
      const float* __restrict__ bh0, const float* __restrict__ bh1,
      const float* __restrict__ bh2, const float* __restrict__ bh3)
{
    int crank = blockIdx.x & (CL - 1);
    int g     = blockIdx.x / CL;
    const float* Whh = (g == 0) ? u0 : (g == 1) ? u1 : (g == 2) ? u2 : u3;
    const float* bhh = (g == 0) ? bh0 : (g == 1) ? bh1 : (g == 2) ? bh2 : bh3;

    int tid = threadIdx.x, wid = tid >> 5, lane = tid & 31;
    int i_base = crank * 32;

    __shared__ ull   sh_w6[16][8][32];   // 32KB: row 5 of each warp
    __shared__ float sh_h[2][H_DIM];
    __shared__ float sh_gh4[96][5];      // 4 partials per row (+pad col)
    __shared__ float sh_hn[32];          // gate output handoff
    __shared__ float sh_bhhn[32];
    __shared__ ull   sh_mbar[2];
    __shared__ uint32_t sh_rh[CL];       // mapa'd peer base of sh_h[0][0]
    __shared__ uint32_t sh_rmb[CL];      // mapa'd peer base of sh_mbar[0]

    // Weights: warp wid owns rows fr = wid*6 .. wid*6+5; row fr -> gate fr>>5,
    // hidden idx i_base + (fr&31). Lane owns column pairs {64*jj + 2*lane, +1}.
    // Rows 0..4 -> registers; row 5 -> sh_w6 (keeps regs <= 128, no spills).
    ull w[5][8];
    int fr0 = wid * 6;
#pragma unroll
    for (int r = 0; r < 5; r++) {
        int fr   = fr0 + r;
        int grow = (fr >> 5) * H_DIM + i_base + (fr & 31);
        const ull* wp = (const ull*)(Whh + (size_t)grow * H_DIM + 2 * lane);
#pragma unroll
        for (int jj = 0; jj < 8; jj++) w[r][jj] = wp[jj * 32];
    }
    {
        int fr   = fr0 + 5;
        int grow = (fr >> 5) * H_DIM + i_base + (fr & 31);
        const ull* wp = (const ull*)(Whh + (size_t)grow * H_DIM + 2 * lane);
#pragma unroll
        for (int jj = 0; jj < 8; jj++) sh_w6[wid][jj][lane] = wp[jj * 32];
    }
    sh_h[0][tid] = 0.f;                       // blockDim == H_DIM
    if (tid < 32) sh_bhhn[tid] = bhh[2 * H_DIM + i_base + tid];

    uint32_t mbar0_l = smem_u32(&sh_mbar[0]);
    uint32_t h_l     = smem_u32(&sh_h[0][0]);
    if (tid == 0) {
        asm volatile("mbarrier.init.shared.b64 [%0], %1;" :: "r"(mbar0_l), "r"(CL) : "memory");
        asm volatile("mbarrier.init.shared.b64 [%0], %1;" :: "r"(mbar0_l + 8), "r"(CL) : "memory");
    }
    if (tid < CL) {
        uint32_t rh, rmb;
        asm("mapa.shared::cluster.u32 %0, %1, %2;" : "=r"(rh)  : "r"(h_l),     "r"(tid));
        asm("mapa.shared::cluster.u32 %0, %1, %2;" : "=r"(rmb) : "r"(mbar0_l), "r"(tid));
        sh_rh[tid]  = rh;
        sh_rmb[tid] = rmb;
    }
    __syncthreads();
    // all CTAs' mbarriers initialized before any remote store/arrive
    asm volatile("barrier.cluster.arrive.aligned;" ::: "memory");
    asm volatile("barrier.cluster.wait.aligned;" ::: "memory");

    const float* gi0    = g_gi + (size_t)g * S_LEN * G3H;
    uint32_t     w6base = smem_u32(&sh_w6[wid][0][lane]);   // +jj*256B per step
    uint32_t     my_rh  = sh_rh[wid];                        // peer this warp serves
    uint32_t     my_rmb = sh_rmb[wid];

    for (int s = 0; s < S_LEN; s++) {
        int p = s & 1;

        // prefetch gi for this step's gates (warp 0 only)
        float gir = 0.f, giz = 0.f, gin = 0.f;
        if (wid == 0) {
            const float* gp = gi0 + (size_t)s * G3H + i_base + lane;
            gir = gp[0];
            giz = gp[H_DIM];
            gin = gp[2 * H_DIM];
        }

        if (s > 0) {
            uint32_t mb = mbar0_l + p * 8;
            uint32_t ph = ((s - 1) >> 1) & 1;
            asm volatile(
                "{\n\t.reg .pred P1;\n\t"
                "WL_%=:\n\t"
                "mbarrier.try_wait.parity.acquire.cluster.shared::cta.b64 P1, [%0], %1, 0x989680;\n\t"
                "@P1 bra.uni WD_%=;\n\t"
                "bra.uni WL_%=;\n\t"
                "WD_%=:\n\t}"
                :: "r"(mb), "r"(ph) : "memory");
        }

        // packed matvec: rows 0..4 from regs, row 5 streamed from SMEM
        ull a0 = 0, a1 = 0, a2 = 0, a3 = 0, a4 = 0, a5 = 0;
        const ull* hrow = (const ull*)&sh_h[p][2 * lane];
#pragma unroll
        for (int jj = 0; jj < 8; jj++) {
            ull hv = hrow[jj * 32];
            ull w5;
            asm("ld.shared.b64 %0, [%1];" : "=l"(w5) : "r"(w6base + jj * 256));
            asm("fma.rn.f32x2 %0, %1, %2, %0;" : "+l"(a0) : "l"(w[0][jj]), "l"(hv));
            asm("fma.rn.f32x2 %0, %1, %2, %0;" : "+l"(a1) : "l"(w[1][jj]), "l"(hv));
            asm("fma.rn.f32x2 %0, %1, %2, %0;" : "+l"(a2) : "l"(w[2][jj]), "l"(hv));
            asm("fma.rn.f32x2 %0, %1, %2, %0;" : "+l"(a3) : "l"(w[3][jj]), "l"(hv));
            asm("fma.rn.f32x2 %0, %1, %2, %0;" : "+l"(a4) : "l"(w[4][jj]), "l"(hv));
            asm("fma.rn.f32x2 %0, %1, %2, %0;" : "+l"(a5) : "l"(w5),       "l"(hv));
        }
        // fold pair halves, repack rows (r0,r1)(r2,r3)(r4,r5); 3-level packed
        // butterfly (off 16,8,4) leaves 4 partials/row, lane c<4 holds group c
        float2 f0 = *(float2*)&a0, f1 = *(float2*)&a1, f2 = *(float2*)&a2;
        float2 f3 = *(float2*)&a3, f4 = *(float2*)&a4, f5 = *(float2*)&a5;
        ull v0, v1, v2;
        asm("mov.b64 %0, {%1, %2};" : "=l"(v0) : "f"(f0.x + f0.y), "f"(f1.x + f1.y));
        asm("mov.b64 %0, {%1, %2};" : "=l"(v1) : "f"(f2.x + f2.y), "f"(f3.x + f3.y));
        asm("mov.b64 %0, {%1, %2};" : "=l"(v2) : "f"(f4.x + f4.y), "f"(f5.x + f5.y));
#pragma unroll
        for (int off = 16; off >= 4; off >>= 1) {
            ull o0 = __shfl_xor_sync(0xffffffffu, v0, off);
            ull o1 = __shfl_xor_sync(0xffffffffu, v1, off);
            ull o2 = __shfl_xor_sync(0xffffffffu, v2, off);
            asm("add.rn.f32x2 %0, %0, %1;" : "+l"(v0) : "l"(o0));
            asm("add.rn.f32x2 %0, %0, %1;" : "+l"(v1) : "l"(o1));
            asm("add.rn.f32x2 %0, %0, %1;" : "+l"(v2) : "l"(o2));
        }
        if (lane < 4) {
            float2 g0 = *(float2*)&v0, g1 = *(float2*)&v1, g2 = *(float2*)&v2;
            sh_gh4[fr0 + 0][lane] = g0.x;
            sh_gh4[fr0 + 1][lane] = g0.y;
            sh_gh4[fr0 + 2][lane] = g1.x;
            sh_gh4[fr0 + 3][lane] = g1.y;
            sh_gh4[fr0 + 4][lane] = g2.x;
            sh_gh4[fr0 + 5][lane] = g2.y;
        }
        __syncthreads();

        // warp 0: finish the 4-wide sums, compute gates, hand off via SMEM
        if (wid == 0) {
            float ghr = (sh_gh4[lane][0] + sh_gh4[lane][1])
                      + (sh_gh4[lane][2] + sh_gh4[lane][3]);
            float ghz = (sh_gh4[32 + lane][0] + sh_gh4[32 + lane][1])
                      + (sh_gh4[32 + lane][2] + sh_gh4[32 + lane][3]);
            float ghn = (sh_gh4[64 + lane][0] + sh_gh4[64 + lane][1])
                      + (sh_gh4[64 + lane][2] + sh_gh4[64 + lane][3]);
            float hold = sh_h[p][i_base + lane];
            float rr = sigf(gir + ghr);
            float zz = sigf(giz + ghz);
            float nn = tanhf_fast(gin + rr * (ghn + sh_bhhn[lane]));
            float hn = (1.f - zz) * nn + zz * hold;
            sh_hn[lane] = hn;
            if (s == S_LEN - 1) g_rep[g * H_DIM + i_base + lane] = hn;
        }
        __syncthreads();

        if (s < S_LEN - 1) {
            // warp w delivers this CTA's slice to peer w (parallel DSMEM)
            float hn = sh_hn[lane];
            uint32_t off = (uint32_t)(((p ^ 1) * H_DIM + i_base + lane) * 4);
            asm volatile("st.shared::cluster.f32 [%0], %1;"
                         :: "r"(my_rh + off), "f"(hn) : "memory");
            __syncwarp();
            if (lane == 0) {
                asm volatile("mbarrier.arrive.release.cluster.shared::cluster.b64 _, [%0];"
                             :: "r"(my_rmb + (uint32_t)((p ^ 1) * 8)) : "memory");
            }
        }
        // no step-end block barrier: readiness signaled by mbar[p^1]
    }
}

// ---------------- kernel 3/4: dense head ----------------
__global__ void k_dense1(const float* __restrict__ w, const float* __restrict__ b) {
    __shared__ float red[128];
    int d = blockIdx.x;
    const float* wr = w + (size_t)d * (4 * H_DIM);
    float s = 0.f;
    for (int k = threadIdx.x; k < 4 * H_DIM; k += 128) s += g_rep[k] * wr[k];
    red[threadIdx.x] = s;
    __syncthreads();
    for (int off = 64; off > 0; off >>= 1) {
        if (threadIdx.x < off) red[threadIdx.x] += red[threadIdx.x + off];
        __syncthreads();
    }
    if (threadIdx.x == 0) g_h1[d] = fmaxf(red[0] + b[d], 0.f);
}

__global__ void k_dense2(const float* __restrict__ w, const float* __restrict__ b,
                         float* __restrict__ out) {
    __shared__ float red[D_DIM];
    int t = threadIdx.x;
    red[t] = g_h1[t] * w[t];
    __syncthreads();
    for (int off = 512; off > 0; off >>= 1) {
        if (t < off) red[t] += red[t + off];
        __syncthreads();
    }
    if (t == 0) out[0] = 1.f / (1.f + __expf(-(red[0] + b[0])));
}

// ---------------- launch ----------------
extern "C" void kernel_launch(void* const* d_in, const int* in_sizes, int n_in,
                              void* d_out, int out_size)
{
    (void)in_sizes; (void)n_in; (void)out_size;
    const void*  sent = d_in[0];
    const float* emb  = (const float*)d_in[1];
    const float *wih[4], *whh[4], *bih[4], *bhh[4];
    for (int g = 0; g < 4; g++) {            // order: ctx_f, ctx_b, qry_f, qry_b
        wih[g] = (const float*)d_in[2 + 4 * g];
        whh[g] = (const float*)d_in[3 + 4 * g];
        bih[g] = (const float*)d_in[4 + 4 * g];
        bhh[g] = (const float*)d_in[5 + 4 * g];
    }
    const float* d1w = (const float*)d_in[18];
    const float* d1b = (const float*)d_in[19];
    const float* d2w = (const float*)d_in[20];
    const float* d2b = (const float*)d_in[21];

    cudaFuncSetAttribute(k_gru, cudaFuncAttributeNonPortableClusterSizeAllowed, 1);

    k_nop<<<1, 32>>>();                      // keeps k_gru inside ncu's capture window

    k_tokens<<<1, S_LEN>>>(sent);

    dim3 ggrid(G3H / 128, S_LEN / 128, 4);   // (12, 8, 4)
    k_gemm_gi<<<ggrid, 256>>>(emb,
                              wih[0], wih[1], wih[2], wih[3],
                              bih[0], bih[1], bih[2], bih[3],
                              bhh[0], bhh[1], bhh[2], bhh[3]);

    k_gru<<<64, 512>>>(whh[0], whh[1], whh[2], whh[3],
                       bhh[0], bhh[1], bhh[2], bhh[3]);

    k_dense1<<<D_DIM, 128>>>(d1w, d1b);
    k_dense2<<<1, D_DIM>>>(d2w, d2b, (float*)d_out);
}

// round 12
// speedup vs baseline: 1.1369x; 1.0883x over previous
#include <cuda_runtime.h>
#include <cstdint>
#include <cstddef>

#define S_LEN 1024
#define E_DIM 512
#define H_DIM 512
#define G3H   1536
#define D_DIM 1024
#define CL    16

typedef unsigned long long ull;

// ---------------- device scratch (static allocation only) ----------------
__device__ int   g_tokens[S_LEN];
__device__ float g_gi[(size_t)4 * S_LEN * G3H];   // 25.2 MB
__device__ float g_rep[4 * H_DIM];
__device__ float g_h1[D_DIM];

// ---------------- helpers ----------------
__device__ __forceinline__ float sigf(float x) { return 1.f / (1.f + __expf(-x)); }
__device__ __forceinline__ float tanhf_fast(float x) { return 2.f / (1.f + __expf(-2.f * x)) - 1.f; }

__device__ __forceinline__ uint32_t smem_u32(const void* p) {
    uint32_t a;
    asm("{ .reg .u64 t; cvta.to.shared.u64 t, %1; cvt.u32.u64 %0, t; }" : "=r"(a) : "l"(p));
    return a;
}

// ---------------- kernel -1: profiling-alignment no-op ----------------
__global__ void k_nop() {}

// ---------------- kernel 0: token dtype normalization ----------------
__global__ void k_tokens(const void* __restrict__ sent) {
    const int*       p32 = (const int*)sent;
    const long long* p64 = (const long long*)sent;
    bool is64 = true;
#pragma unroll
    for (int k = 0; k < 8; k++) {
        int lo = p32[2 * k], hi = p32[2 * k + 1];
        if (hi != 0 || lo < 0 || lo >= 50257) is64 = false;
    }
    int t = threadIdx.x;
    g_tokens[t] = is64 ? (int)p64[t] : p32[t];
}

// ---------------- kernel 1: gi = x @ Wih^T + bih (+ bhh folded for r,z) ----
__global__ __launch_bounds__(256, 2) void k_gemm_gi(
    const float* __restrict__ emb,
    const float* __restrict__ w0, const float* __restrict__ w1,
    const float* __restrict__ w2, const float* __restrict__ w3,
    const float* __restrict__ bi0, const float* __restrict__ bi1,
    const float* __restrict__ bi2, const float* __restrict__ bi3,
    const float* __restrict__ bh0, const float* __restrict__ bh1,
    const float* __restrict__ bh2, const float* __restrict__ bh3)
{
    int g = blockIdx.z;
    const float* Wih = (g == 0) ? w0 : (g == 1) ? w1 : (g == 2) ? w2 : w3;
    const float* bih = (g == 0) ? bi0 : (g == 1) ? bi1 : (g == 2) ? bi2 : bi3;
    const float* bhh = (g == 0) ? bh0 : (g == 1) ? bh1 : (g == 2) ? bh2 : bh3;

    int s0 = blockIdx.y * 128;
    int j0 = blockIdx.x * 128;
    int rev = g & 1;

    __shared__ float As[8][128];
    __shared__ float Bs[8][128];
    __shared__ int   toks[128];

    int tid = threadIdx.x;
    if (tid < 128) {
        int s = s0 + tid;
        toks[tid] = g_tokens[rev ? (S_LEN - 1 - s) : s];
    }
    __syncthreads();

    int tx = tid & 15, ty = tid >> 4;
    float acc[8][8];
#pragma unroll
    for (int i = 0; i < 8; i++)
#pragma unroll
        for (int j = 0; j < 8; j++) acc[i][j] = 0.f;

    int lrow = tid >> 1;
    int kq   = (tid & 1) * 4;
    const float* bptr = Wih + (size_t)(j0 + lrow) * E_DIM + kq;

    for (int kk = 0; kk < E_DIM; kk += 8) {
        float4 av = *(const float4*)(emb + (size_t)toks[lrow] * E_DIM + kk + kq);
        float4 bv = *(const float4*)(bptr + kk);
        As[kq + 0][lrow] = av.x; As[kq + 1][lrow] = av.y;
        As[kq + 2][lrow] = av.z; As[kq + 3][lrow] = av.w;
        Bs[kq + 0][lrow] = bv.x; Bs[kq + 1][lrow] = bv.y;
        Bs[kq + 2][lrow] = bv.z; Bs[kq + 3][lrow] = bv.w;
        __syncthreads();
#pragma unroll
        for (int k = 0; k < 8; k++) {
            float ar[8], br[8];
            *(float4*)&ar[0] = *(const float4*)&As[k][ty * 8];
            *(float4*)&ar[4] = *(const float4*)&As[k][ty * 8 + 4];
            *(float4*)&br[0] = *(const float4*)&Bs[k][tx * 8];
            *(float4*)&br[4] = *(const float4*)&Bs[k][tx * 8 + 4];
#pragma unroll
            for (int i = 0; i < 8; i++)
#pragma unroll
                for (int j = 0; j < 8; j++) acc[i][j] += ar[i] * br[j];
        }
        __syncthreads();
    }

#pragma unroll
    for (int i = 0; i < 8; i++) {
        int s = s0 + ty * 8 + i;
        float* orow = g_gi + ((size_t)g * S_LEN + s) * G3H;
#pragma unroll
        for (int j = 0; j < 8; j++) {
            int jg = j0 + tx * 8 + j;
            float bias = bih[jg] + (jg < 2 * H_DIM ? bhh[jg] : 0.f);
            orow[jg] = acc[i][j] + bias;
        }
    }
}

// ---------------- kernel 2: recurrent GRU, 4 clusters x 16 CTAs -------------
// R7 structure with SINGLE-WAITER exchange: only warp 0 executes the
// cluster-acquire mbarrier wait; a bar.sync then releases the other 15 warps
// (warp0's acquire + barrier ordering gives CTA-wide visibility). Removes 15
// concurrent cluster-scope waits per step.
__global__ void __cluster_dims__(CL, 1, 1) __launch_bounds__(512, 1)
k_gru(const float* __restrict__ u0, const float* __restrict__ u1,
      const float* __restrict__ u2, const float* __restrict__ u3,
      const float* __restrict__ bh0, const float* __restrict__ bh1,
      const float* __restrict__ bh2, const float* __restrict__ bh3)
{
    int crank = blockIdx.x & (CL - 1);
    int g     = blockIdx.x / CL;
    const float* Whh = (g == 0) ? u0 : (g == 1) ? u1 : (g == 2) ? u2 : u3;
    const float* bhh = (g == 0) ? bh0 : (g == 1) ? bh1 : (g == 2) ? bh2 : bh3;

    int tid = threadIdx.x, wid = tid >> 5, lane = tid & 31;
    int i_base = crank * 32;

    __shared__ ull   sh_w6[16][8][32];   // 32KB: row 5 of each warp
    __shared__ float sh_h[2][H_DIM];
    __shared__ float sh_gh[96];
    __shared__ float sh_bhhn[32];
    __shared__ ull   sh_mbar[2];
    __shared__ uint32_t sh_rh[CL];       // mapa'd peer base of sh_h[0][0]
    __shared__ uint32_t sh_rmb[CL];      // mapa'd peer base of sh_mbar[0]

    // Weights: warp wid owns rows fr = wid*6 .. wid*6+5; row fr -> gate fr>>5,
    // hidden idx i_base + (fr&31). Lane owns column pairs {64*jj + 2*lane, +1}.
    // Rows 0..4 -> registers; row 5 -> sh_w6 (keeps regs <= 128, no spills).
    ull w[5][8];
    int fr0 = wid * 6;
#pragma unroll
    for (int r = 0; r < 5; r++) {
        int fr   = fr0 + r;
        int grow = (fr >> 5) * H_DIM + i_base + (fr & 31);
        const ull* wp = (const ull*)(Whh + (size_t)grow * H_DIM + 2 * lane);
#pragma unroll
        for (int jj = 0; jj < 8; jj++) w[r][jj] = wp[jj * 32];
    }
    {
        int fr   = fr0 + 5;
        int grow = (fr >> 5) * H_DIM + i_base + (fr & 31);
        const ull* wp = (const ull*)(Whh + (size_t)grow * H_DIM + 2 * lane);
#pragma unroll
        for (int jj = 0; jj < 8; jj++) sh_w6[wid][jj][lane] = wp[jj * 32];
    }
    sh_h[0][tid] = 0.f;                       // blockDim == H_DIM
    if (tid < 32) sh_bhhn[tid] = bhh[2 * H_DIM + i_base + tid];

    uint32_t mbar0_l = smem_u32(&sh_mbar[0]);
    uint32_t h_l     = smem_u32(&sh_h[0][0]);
    if (tid == 0) {
        asm volatile("mbarrier.init.shared.b64 [%0], %1;" :: "r"(mbar0_l), "r"(CL) : "memory");
        asm volatile("mbarrier.init.shared.b64 [%0], %1;" :: "r"(mbar0_l + 8), "r"(CL) : "memory");
    }
    if (tid < CL) {
        uint32_t rh, rmb;
        asm("mapa.shared::cluster.u32 %0, %1, %2;" : "=r"(rh)  : "r"(h_l),     "r"(tid));
        asm("mapa.shared::cluster.u32 %0, %1, %2;" : "=r"(rmb) : "r"(mbar0_l), "r"(tid));
        sh_rh[tid]  = rh;
        sh_rmb[tid] = rmb;
    }
    __syncthreads();
    // all CTAs' mbarriers initialized before any remote store/arrive
    asm volatile("barrier.cluster.arrive.aligned;" ::: "memory");
    asm volatile("barrier.cluster.wait.aligned;" ::: "memory");

    const float* gi0    = g_gi + (size_t)g * S_LEN * G3H;
    uint32_t     w6base = smem_u32(&sh_w6[wid][0][lane]);   // +jj*256B per step

    for (int s = 0; s < S_LEN; s++) {
        int p = s & 1;

        // prefetch gi for this step's epilogue (warp 0 only; L2 hides under wait)
        float gir = 0.f, giz = 0.f, gin = 0.f;
        if (wid == 0) {
            const float* gp = gi0 + (size_t)s * G3H + i_base + lane;
            gir = gp[0];
            giz = gp[H_DIM];
            gin = gp[2 * H_DIM];

            if (s > 0) {
                // SINGLE waiter: warp 0 only, full cluster-acquire
                uint32_t mb = mbar0_l + p * 8;
                uint32_t ph = ((s - 1) >> 1) & 1;
                asm volatile(
                    "{\n\t.reg .pred P1;\n\t"
                    "WL_%=:\n\t"
                    "mbarrier.try_wait.parity.acquire.cluster.shared::cta.b64 P1, [%0], %1, 0x989680;\n\t"
                    "@P1 bra.uni WD_%=;\n\t"
                    "bra.uni WL_%=;\n\t"
                    "WD_%=:\n\t}"
                    :: "r"(mb), "r"(ph) : "memory");
            }
        }
        // release the other 15 warps once warp 0 has observed the phase flip
        __syncthreads();

        // packed matvec: rows 0..4 from regs, row 5 streamed from SMEM
        ull a0 = 0, a1 = 0, a2 = 0, a3 = 0, a4 = 0, a5 = 0;
        const ull* hrow = (const ull*)&sh_h[p][2 * lane];
#pragma unroll
        for (int jj = 0; jj < 8; jj++) {
            ull hv = hrow[jj * 32];
            ull w5;
            asm("ld.shared.b64 %0, [%1];" : "=l"(w5) : "r"(w6base + jj * 256));
            asm("fma.rn.f32x2 %0, %1, %2, %0;" : "+l"(a0) : "l"(w[0][jj]), "l"(hv));
            asm("fma.rn.f32x2 %0, %1, %2, %0;" : "+l"(a1) : "l"(w[1][jj]), "l"(hv));
            asm("fma.rn.f32x2 %0, %1, %2, %0;" : "+l"(a2) : "l"(w[2][jj]), "l"(hv));
            asm("fma.rn.f32x2 %0, %1, %2, %0;" : "+l"(a3) : "l"(w[3][jj]), "l"(hv));
            asm("fma.rn.f32x2 %0, %1, %2, %0;" : "+l"(a4) : "l"(w[4][jj]), "l"(hv));
            asm("fma.rn.f32x2 %0, %1, %2, %0;" : "+l"(a5) : "l"(w5),       "l"(hv));
        }
        // fold pair halves, repack rows (r0,r1)(r2,r3)(r4,r5), packed butterfly
        float2 f0 = *(float2*)&a0, f1 = *(float2*)&a1, f2 = *(float2*)&a2;
        float2 f3 = *(float2*)&a3, f4 = *(float2*)&a4, f5 = *(float2*)&a5;
        ull v0, v1, v2;
        asm("mov.b64 %0, {%1, %2};" : "=l"(v0) : "f"(f0.x + f0.y), "f"(f1.x + f1.y));
        asm("mov.b64 %0, {%1, %2};" : "=l"(v1) : "f"(f2.x + f2.y), "f"(f3.x + f3.y));
        asm("mov.b64 %0, {%1, %2};" : "=l"(v2) : "f"(f4.x + f4.y), "f"(f5.x + f5.y));
#pragma unroll
        for (int off = 16; off > 0; off >>= 1) {
            ull o0 = __shfl_xor_sync(0xffffffffu, v0, off);
            ull o1 = __shfl_xor_sync(0xffffffffu, v1, off);
            ull o2 = __shfl_xor_sync(0xffffffffu, v2, off);
            asm("add.rn.f32x2 %0, %0, %1;" : "+l"(v0) : "l"(o0));
            asm("add.rn.f32x2 %0, %0, %1;" : "+l"(v1) : "l"(o1));
            asm("add.rn.f32x2 %0, %0, %1;" : "+l"(v2) : "l"(o2));
        }
        if (lane == 0) {
            *(ull*)&sh_gh[fr0 + 0] = v0;   // fr0 = 6*wid -> 8B aligned
            *(ull*)&sh_gh[fr0 + 2] = v1;
            *(ull*)&sh_gh[fr0 + 4] = v2;
        }
        __syncthreads();

        if (wid == 0) {
            float hold = sh_h[p][i_base + lane];
            float ghr  = sh_gh[lane];
            float ghz  = sh_gh[32 + lane];
            float ghn  = sh_gh[64 + lane];
            float rr = sigf(gir + ghr);
            float zz = sigf(giz + ghz);
            float nn = tanhf_fast(gin + rr * (ghn + sh_bhhn[lane]));
            float hn = (1.f - zz) * nn + zz * hold;

            if (s == S_LEN - 1) {
                g_rep[g * H_DIM + i_base + lane] = hn;
            } else {
                // broadcast h_new to every CTA's next buffer (R7-validated)
                uint32_t off = (uint32_t)(((p ^ 1) * H_DIM + i_base + lane) * 4);
#pragma unroll
                for (int rk = 0; rk < CL; rk++) {
                    asm volatile("st.shared::cluster.f32 [%0], %1;"
                                 :: "r"(sh_rh[rk] + off), "f"(hn) : "memory");
                }
                __syncwarp();
                if (lane == 0) {
                    uint32_t mboff = (uint32_t)((p ^ 1) * 8);
#pragma unroll
                    for (int rk = 0; rk < CL; rk++) {
                        asm volatile("mbarrier.arrive.shared::cluster.b64 _, [%0];"
                                     :: "r"(sh_rmb[rk] + mboff) : "memory");
                    }
                }
            }
        }
        // no step-end block barrier: readiness signaled by mbar[p^1]
    }
}

// ---------------- kernel 3/4: dense head ----------------
__global__ void k_dense1(const float* __restrict__ w, const float* __restrict__ b) {
    __shared__ float red[128];
    int d = blockIdx.x;
    const float* wr = w + (size_t)d * (4 * H_DIM);
    float s = 0.f;
    for (int k = threadIdx.x; k < 4 * H_DIM; k += 128) s += g_rep[k] * wr[k];
    red[threadIdx.x] = s;
    __syncthreads();
    for (int off = 64; off > 0; off >>= 1) {
        if (threadIdx.x < off) red[threadIdx.x] += red[threadIdx.x + off];
        __syncthreads();
    }
    if (threadIdx.x == 0) g_h1[d] = fmaxf(red[0] + b[d], 0.f);
}

__global__ void k_dense2(const float* __restrict__ w, const float* __restrict__ b,
                         float* __restrict__ out) {
    __shared__ float red[D_DIM];
    int t = threadIdx.x;
    red[t] = g_h1[t] * w[t];
    __syncthreads();
    for (int off = 512; off > 0; off >>= 1) {
        if (t < off) red[t] += red[t + off];
        __syncthreads();
    }
    if (t == 0) out[0] = 1.f / (1.f + __expf(-(red[0] + b[0])));
}

// ---------------- launch ----------------
extern "C" void kernel_launch(void* const* d_in, const int* in_sizes, int n_in,
                              void* d_out, int out_size)
{
    (void)in_sizes; (void)n_in; (void)out_size;
    const void*  sent = d_in[0];
    const float* emb  = (const float*)d_in[1];
    const float *wih[4], *whh[4], *bih[4], *bhh[4];
    for (int g = 0; g < 4; g++) {            // order: ctx_f, ctx_b, qry_f, qry_b
        wih[g] = (const float*)d_in[2 + 4 * g];
        whh[g] = (const float*)d_in[3 + 4 * g];
        bih[g] = (const float*)d_in[4 + 4 * g];
        bhh[g] = (const float*)d_in[5 + 4 * g];
    }
    const float* d1w = (const float*)d_in[18];
    const float* d1b = (const float*)d_in[19];
    const float* d2w = (const float*)d_in[20];
    const float* d2b = (const float*)d_in[21];

    cudaFuncSetAttribute(k_gru, cudaFuncAttributeNonPortableClusterSizeAllowed, 1);

    k_nop<<<1, 32>>>();                      // keeps k_gru inside ncu's capture window

    k_tokens<<<1, S_LEN>>>(sent);

    dim3 ggrid(G3H / 128, S_LEN / 128, 4);   // (12, 8, 4)
    k_gemm_gi<<<ggrid, 256>>>(emb,
                              wih[0], wih[1], wih[2], wih[3],
                              bih[0], bih[1], bih[2], bih[3],
                              bhh[0], bhh[1], bhh[2], bhh[3]);

    k_gru<<<64, 512>>>(whh[0], whh[1], whh[2], whh[3],
                       bhh[0], bhh[1], bhh[2], bhh[3]);

    k_dense1<<<D_DIM, 128>>>(d1w, d1b);
    k_dense2<<<1, D_DIM>>>(d2w, d2b, (float*)d_out);
}